// round 4
// baseline (speedup 1.0000x reference)
#include <cuda_runtime.h>
#include <cstdint>
#include <cstddef>

#define BATCH  64
#define TSTEPS 1000
#define NG     2
#define HH     160      // hidden per group (STEP)
#define DD     320      // NG*HH
#define NGATE  640      // 4*HH
#define NCH    64
#define NF     5

// ---- recurrence config: 320 threads, 2 gate-columns per thread ----
#define RNT 320
#define RSK 88          // k-rows whose weights live in smem
#define RRK 72          // k-rows whose weights live in registers
#define REC_SMEM ((RSK/4)*RNT*2*16 + 2*HH*4)   // 225280 + 1280 = 226560 B

// ---------------- scratch (static device globals) ----------------
__device__ float  g_x1[(size_t)BATCH * TSTEPS * DD];
__device__ float  g_x2[(size_t)BATCH * TSTEPS * DD];
__device__ float  g_gates[(size_t)BATCH * TSTEPS * NG * NGATE];
__device__ float4 g_wsm[NG * (RSK/4) * RNT * 2];   // prepped smem-part weights
__device__ float  g_wrg[NG * RRK * RNT * 2];       // prepped reg-part weights

// ---------------- transpose: [B,C,T,F] -> [B*T, C*F] ----------------
__global__ void transpose_kernel(const float* __restrict__ in)
{
    size_t idx = (size_t)blockIdx.x * blockDim.x + threadIdx.x;
    if (idx >= (size_t)BATCH * NCH * TSTEPS * NF) return;
    int f = (int)(idx % NF);
    size_t r = idx / NF;
    int t = (int)(r % TSTEPS); r /= TSTEPS;
    int c = (int)(r % NCH);    r /= NCH;
    int b = (int)r;
    g_x1[((size_t)(b * TSTEPS + t)) * DD + c * NF + f] = in[idx];
}

// ---------------- weight prep: permute Whh into coalesced rec layout ----------------
// thread t of rec block (t = 2u+r) owns gate columns c0=(2r)*HH+u, c1=(2r+1)*HH+u.
__global__ void prep_kernel(const float* __restrict__ Whh)
{
    int idx = blockIdx.x * blockDim.x + threadIdx.x;
    if (idx >= NG * HH * NGATE) return;
    int cidx = idx % NGATE;
    int k    = (idx / NGATE) % HH;
    int g    = idx / (NGATE * HH);
    float w = Whh[idx];
    int u = cidx % HH, q = cidx / HH;        // q: gate index (i,f,g,o)
    int r = q >> 1, col = q & 1;
    int tt = 2 * u + r;
    if (k < RSK) {
        ((float*)g_wsm)[(((g * (RSK/4) + (k >> 2)) * RNT + tt) * 2 + col) * 4 + (k & 3)] = w;
    } else {
        g_wrg[((g * RRK + (k - RSK)) * RNT + tt) * 2 + col] = w;
    }
}

// ---------------- pre-GEMM: 128x64 tile, 256 threads, 8x4 per thread ----------------
template <int STAGE>
__global__ __launch_bounds__(256) void pregemm_kernel(const float* __restrict__ W,
                                                      const float* __restrict__ bias)
{
    __shared__ float As[16][132];   // [k][m] (k-major so A reads are float4 over m)
    __shared__ float Bs[16][64];    // [k][n]

    const float* X = (STAGE == 1) ? g_x1 : g_x2;

    const int m0 = blockIdx.x * 128;
    const int n0 = blockIdx.y * 64;
    const int g  = blockIdx.z;
    const int tid = threadIdx.x;
    const int tm = tid >> 4;            // 0..15 -> 8 m-rows each
    const int tn = tid & 15;            // 0..15 -> 4 n-cols each

    const int rowA = tid >> 1;          // 0..127
    const int kqA  = (tid & 1) * 8;     // 0 or 8
    const int kB   = tid >> 4;          // 0..15
    const int nqB  = (tid & 15) * 4;    // 0..60

    const float* Xp = X + (size_t)(m0 + rowA) * DD + g * HH + kqA;
    const float* Wp = W + (size_t)g * HH * NGATE + (size_t)kB * NGATE + n0 + nqB;

    float acc[8][4];
#pragma unroll
    for (int i = 0; i < 8; i++)
#pragma unroll
        for (int j = 0; j < 4; j++) acc[i][j] = 0.f;

    for (int k0 = 0; k0 < HH; k0 += 16) {
        float4 x0 = *(const float4*)(Xp + k0);
        float4 x1 = *(const float4*)(Xp + k0 + 4);
        As[kqA + 0][rowA] = x0.x;
        As[kqA + 1][rowA] = x0.y;
        As[kqA + 2][rowA] = x0.z;
        As[kqA + 3][rowA] = x0.w;
        As[kqA + 4][rowA] = x1.x;
        As[kqA + 5][rowA] = x1.y;
        As[kqA + 6][rowA] = x1.z;
        As[kqA + 7][rowA] = x1.w;
        *(float4*)&Bs[kB][nqB] = *(const float4*)(Wp + (size_t)k0 * NGATE);
        __syncthreads();
#pragma unroll
        for (int k = 0; k < 16; k++) {
            float4 a0 = *(const float4*)&As[k][tm * 8];
            float4 a1 = *(const float4*)&As[k][tm * 8 + 4];
            float4 bv = *(const float4*)&Bs[k][tn * 4];
            float av[8] = {a0.x, a0.y, a0.z, a0.w, a1.x, a1.y, a1.z, a1.w};
#pragma unroll
            for (int i = 0; i < 8; i++) {
                acc[i][0] = fmaf(av[i], bv.x, acc[i][0]);
                acc[i][1] = fmaf(av[i], bv.y, acc[i][1]);
                acc[i][2] = fmaf(av[i], bv.z, acc[i][2]);
                acc[i][3] = fmaf(av[i], bv.w, acc[i][3]);
            }
        }
        __syncthreads();
    }

    float4 bb = *(const float4*)(bias + g * NGATE + n0 + tn * 4);
#pragma unroll
    for (int i = 0; i < 8; i++) {
        int m = m0 + tm * 8 + i;
        float4 o;
        o.x = acc[i][0] + bb.x;
        o.y = acc[i][1] + bb.y;
        o.z = acc[i][2] + bb.z;
        o.w = acc[i][3] + bb.w;
        *(float4*)(g_gates + ((size_t)m * NG + g) * NGATE + n0 + tn * 4) = o;
    }
}

// ---------------- recurrence ----------------
// 320 threads; thread 2u+r owns gate columns (2r)*HH+u and (2r+1)*HH+u.
// r=0 -> (i,f); r=1 -> (g,o).  4 gates of unit u sit in adjacent lanes.
template <int STAGE>
__global__ __launch_bounds__(RNT, 1) void rec_kernel(float* __restrict__ out)
{
    extern __shared__ float sm[];
    float4* wsm = (float4*)sm;                   // [RSK/4][RNT][2]
    float*  h_sm = sm + (RSK/4) * RNT * 2 * 4;   // [2][HH] double-buffered

    const int t_ = threadIdx.x;
    const int u  = t_ >> 1;
    const int r  = t_ & 1;
    const int b  = blockIdx.x >> 1;
    const int g  = blockIdx.x & 1;

    // coalesced load of prepped smem-part weights
    const float4* wsrc = g_wsm + (size_t)g * (RSK/4) * RNT * 2;
#pragma unroll 4
    for (int i = t_; i < (RSK/4) * RNT * 2; i += RNT) wsm[i] = wsrc[i];

    // coalesced load of reg-part weights
    float w0[RRK], w1[RRK];
    const float2* wrsrc = (const float2*)g_wrg + (size_t)g * RRK * RNT + t_;
#pragma unroll
    for (int j = 0; j < RRK; j++) {
        float2 v = wrsrc[(size_t)j * RNT];
        w0[j] = v.x; w1[j] = v.y;
    }

    h_sm[t_] = 0.f;   // RNT == 2*HH: zero both h buffers
    float c = 0.f;
    __syncthreads();

    const int c0 = (2 * r) * HH + u;
    const int c1 = (2 * r + 1) * HH + u;
    const float* grow = g_gates + ((size_t)b * TSTEPS) * NG * NGATE + (size_t)g * NGATE;
    float gx0 = grow[c0], gx1 = grow[c1];
    int p = 0;

    for (int t = 0; t < TSTEPS; t++) {
        float nx0 = 0.f, nx1 = 0.f;
        if (t + 1 < TSTEPS) {
            const float* gn = grow + (size_t)(t + 1) * NG * NGATE;
            nx0 = __ldg(gn + c0);
            nx1 = __ldg(gn + c1);
        }

        const float4* h4 = (const float4*)(h_sm + p * HH);
        const float4* wp = wsm + t_ * 2;
        float a0 = gx0, e0 = 0.f, a1 = gx1, e1 = 0.f;
#pragma unroll
        for (int kk = 0; kk < RSK / 4; kk++) {
            float4 hv = h4[kk];
            float4 wa = wp[kk * RNT * 2];
            float4 wb = wp[kk * RNT * 2 + 1];
            a0 = fmaf(wa.x, hv.x, a0); e0 = fmaf(wa.y, hv.y, e0);
            a0 = fmaf(wa.z, hv.z, a0); e0 = fmaf(wa.w, hv.w, e0);
            a1 = fmaf(wb.x, hv.x, a1); e1 = fmaf(wb.y, hv.y, e1);
            a1 = fmaf(wb.z, hv.z, a1); e1 = fmaf(wb.w, hv.w, e1);
        }
#pragma unroll
        for (int jj = 0; jj < RRK / 4; jj++) {
            float4 hv = h4[RSK / 4 + jj];
            a0 = fmaf(w0[4*jj+0], hv.x, a0); e0 = fmaf(w0[4*jj+1], hv.y, e0);
            a0 = fmaf(w0[4*jj+2], hv.z, a0); e0 = fmaf(w0[4*jj+3], hv.w, e0);
            a1 = fmaf(w1[4*jj+0], hv.x, a1); e1 = fmaf(w1[4*jj+1], hv.y, e1);
            a1 = fmaf(w1[4*jj+2], hv.z, a1); e1 = fmaf(w1[4*jj+3], hv.w, e1);
        }
        float acc0 = a0 + e0, acc1 = a1 + e1;

        // col0: r=0 -> i (sigmoid), r=1 -> g (tanh = 2*sigmoid(2x)-1)
        // col1: r=0 -> f (sigmoid), r=1 -> o (sigmoid)
        float z0 = r ? 2.f * acc0 : acc0;
        float s0 = __fdividef(1.f, 1.f + __expf(-z0));
        float A0 = r ? fmaf(2.f, s0, -1.f) : s0;
        float A1 = __fdividef(1.f, 1.f + __expf(-acc1));
        float X0 = __shfl_xor_sync(0xFFFFFFFFu, A0, 1);
        float X1 = __shfl_xor_sync(0xFFFFFFFFu, A1, 1);
        float gi = r ? X0 : A0;
        float gf = r ? X1 : A1;
        float gg = r ? A0 : X0;
        float go = r ? A1 : X1;
        c = fmaf(gf, c, gi * gg);
        float th = __fdividef(2.f, 1.f + __expf(-2.f * c)) - 1.f;
        float hval = go * th;

        if (r == 0) {
            h_sm[(p ^ 1) * HH + u] = hval;
            if (STAGE == 1) {
                int i5 = u / NF, f5 = u - i5 * NF;
                g_x2[((size_t)b * TSTEPS + t) * DD + i5 * 10 + g * NF + f5] = hval;
            } else {
                int d = g * HH + u;
                int cc = d / NF, f5 = d - cc * NF;
                out[(((size_t)b * NCH + cc) * TSTEPS + t) * NF + f5] = hval;
            }
        }
        __syncthreads();
        gx0 = nx0; gx1 = nx1;
        p ^= 1;
    }
}

// ---------------- launch ----------------
extern "C" void kernel_launch(void* const* d_in, const int* in_sizes, int n_in,
                              void* d_out, int out_size)
{
    (void)in_sizes; (void)n_in; (void)out_size;
    const float* input = (const float*)d_in[0];
    const float* Wih1  = (const float*)d_in[1];
    const float* Whh1  = (const float*)d_in[2];
    const float* b1    = (const float*)d_in[3];
    const float* Wih2  = (const float*)d_in[4];
    const float* Whh2  = (const float*)d_in[5];
    const float* b2    = (const float*)d_in[6];
    float* out = (float*)d_out;

    cudaFuncSetAttribute(rec_kernel<1>, cudaFuncAttributeMaxDynamicSharedMemorySize, REC_SMEM);
    cudaFuncSetAttribute(rec_kernel<2>, cudaFuncAttributeMaxDynamicSharedMemorySize, REC_SMEM);

    const int n_in_elems = BATCH * NCH * TSTEPS * NF;
    transpose_kernel<<<(n_in_elems + 255) / 256, 256>>>(input);

    const int n_w = NG * HH * NGATE;
    dim3 gg(BATCH * TSTEPS / 128, NGATE / 64, NG);

    prep_kernel<<<(n_w + 255) / 256, 256>>>(Whh1);
    pregemm_kernel<1><<<gg, 256>>>(Wih1, b1);
    rec_kernel<1><<<BATCH * NG, RNT, REC_SMEM>>>(nullptr);

    prep_kernel<<<(n_w + 255) / 256, 256>>>(Whh2);
    pregemm_kernel<2><<<gg, 256>>>(Wih2, b2);
    rec_kernel<2><<<BATCH * NG, RNT, REC_SMEM>>>(out);
}

// round 5
// speedup vs baseline: 1.2930x; 1.2930x over previous
#include <cuda_runtime.h>
#include <cstdint>
#include <cstddef>

#define BATCH  64
#define TSTEPS 1000
#define NG     2
#define HH     160      // hidden per group (STEP)
#define DD     320      // NG*HH
#define NGATE  640      // 4*HH
#define NCH    64
#define NF     5

// ---- recurrence config: 320 threads, 2 gate-columns per thread ----
#define RNT 320
#define RSK 88          // k-rows whose weights live in smem
#define RRK 72          // k-rows whose weights live in registers
#define PLANE ((RSK/4)*RNT)                    // float4s per weight plane (22*320 = 7040)
#define REC_SMEM (2*PLANE*16 + 2*HH*4)         // 225280 + 1280 = 226560 B

// ---------------- scratch (static device globals) ----------------
__device__ float  g_x1[(size_t)BATCH * TSTEPS * DD];
__device__ float  g_x2[(size_t)BATCH * TSTEPS * DD];
__device__ float  g_gates[(size_t)BATCH * TSTEPS * NG * NGATE];
__device__ float4 g_wsm[NG * 2 * PLANE];       // prepped smem-part weights, 2 planes per group
__device__ float  g_wrg[NG * RRK * RNT * 2];   // prepped reg-part weights

// ---------------- transpose: [B,C,T,F] -> [B*T, C*F] ----------------
__global__ void transpose_kernel(const float* __restrict__ in)
{
    size_t idx = (size_t)blockIdx.x * blockDim.x + threadIdx.x;
    if (idx >= (size_t)BATCH * NCH * TSTEPS * NF) return;
    int f = (int)(idx % NF);
    size_t r = idx / NF;
    int t = (int)(r % TSTEPS); r /= TSTEPS;
    int c = (int)(r % NCH);    r /= NCH;
    int b = (int)r;
    g_x1[((size_t)(b * TSTEPS + t)) * DD + c * NF + f] = in[idx];
}

// ---------------- weight prep: permute Whh into conflict-free rec layout ----------
// rec thread t = 2u+r owns gate columns c0=(2r)*HH+u (plane 0), c1=(2r+1)*HH+u (plane 1).
// plane layout: [kk][tt] float4 over 4 consecutive k  -> thread stride 16B (conflict-free).
__global__ void prep_kernel(const float* __restrict__ Whh)
{
    int idx = blockIdx.x * blockDim.x + threadIdx.x;
    if (idx >= NG * HH * NGATE) return;
    int cidx = idx % NGATE;
    int k    = (idx / NGATE) % HH;
    int g    = idx / (NGATE * HH);
    float w = Whh[idx];
    int u = cidx % HH, q = cidx / HH;        // q: gate index (i,f,g,o)
    int r = q >> 1, col = q & 1;             // col selects plane
    int tt = 2 * u + r;
    if (k < RSK) {
        ((float*)g_wsm)[(((size_t)(g * 2 + col) * (RSK/4) + (k >> 2)) * RNT + tt) * 4 + (k & 3)] = w;
    } else {
        g_wrg[((size_t)(g * RRK + (k - RSK)) * RNT + tt) * 2 + col] = w;
    }
}

// ---------------- pre-GEMM: 128x64 tile, 256 threads, 8x4 per thread ----------------
template <int STAGE>
__global__ __launch_bounds__(256) void pregemm_kernel(const float* __restrict__ W,
                                                      const float* __restrict__ bias)
{
    __shared__ float As[16][132];   // [k][m] (k-major so A reads are float4 over m)
    __shared__ float Bs[16][64];    // [k][n]

    const float* X = (STAGE == 1) ? g_x1 : g_x2;

    const int m0 = blockIdx.x * 128;
    const int n0 = blockIdx.y * 64;
    const int g  = blockIdx.z;
    const int tid = threadIdx.x;
    const int tm = tid >> 4;            // 0..15 -> 8 m-rows each
    const int tn = tid & 15;            // 0..15 -> 4 n-cols each

    const int rowA = tid >> 1;          // 0..127
    const int kqA  = (tid & 1) * 8;     // 0 or 8
    const int kB   = tid >> 4;          // 0..15
    const int nqB  = (tid & 15) * 4;    // 0..60

    const float* Xp = X + (size_t)(m0 + rowA) * DD + g * HH + kqA;
    const float* Wp = W + (size_t)g * HH * NGATE + (size_t)kB * NGATE + n0 + nqB;

    float acc[8][4];
#pragma unroll
    for (int i = 0; i < 8; i++)
#pragma unroll
        for (int j = 0; j < 4; j++) acc[i][j] = 0.f;

    for (int k0 = 0; k0 < HH; k0 += 16) {
        float4 x0 = *(const float4*)(Xp + k0);
        float4 x1 = *(const float4*)(Xp + k0 + 4);
        As[kqA + 0][rowA] = x0.x;
        As[kqA + 1][rowA] = x0.y;
        As[kqA + 2][rowA] = x0.z;
        As[kqA + 3][rowA] = x0.w;
        As[kqA + 4][rowA] = x1.x;
        As[kqA + 5][rowA] = x1.y;
        As[kqA + 6][rowA] = x1.z;
        As[kqA + 7][rowA] = x1.w;
        *(float4*)&Bs[kB][nqB] = *(const float4*)(Wp + (size_t)k0 * NGATE);
        __syncthreads();
#pragma unroll
        for (int k = 0; k < 16; k++) {
            float4 a0 = *(const float4*)&As[k][tm * 8];
            float4 a1 = *(const float4*)&As[k][tm * 8 + 4];
            float4 bv = *(const float4*)&Bs[k][tn * 4];
            float av[8] = {a0.x, a0.y, a0.z, a0.w, a1.x, a1.y, a1.z, a1.w};
#pragma unroll
            for (int i = 0; i < 8; i++) {
                acc[i][0] = fmaf(av[i], bv.x, acc[i][0]);
                acc[i][1] = fmaf(av[i], bv.y, acc[i][1]);
                acc[i][2] = fmaf(av[i], bv.z, acc[i][2]);
                acc[i][3] = fmaf(av[i], bv.w, acc[i][3]);
            }
        }
        __syncthreads();
    }

    float4 bb = *(const float4*)(bias + g * NGATE + n0 + tn * 4);
#pragma unroll
    for (int i = 0; i < 8; i++) {
        int m = m0 + tm * 8 + i;
        float4 o;
        o.x = acc[i][0] + bb.x;
        o.y = acc[i][1] + bb.y;
        o.z = acc[i][2] + bb.z;
        o.w = acc[i][3] + bb.w;
        *(float4*)(g_gates + ((size_t)m * NG + g) * NGATE + n0 + tn * 4) = o;
    }
}

// ---------------- recurrence ----------------
// 320 threads; thread 2u+r owns gate columns (2r)*HH+u and (2r+1)*HH+u.
// r=0 -> (i,f); r=1 -> (g,o).  The 4 gates of unit u sit in adjacent lanes ->
// gate exchange via 2x shfl_xor(1); single __syncthreads per step.
template <int STAGE>
__global__ __launch_bounds__(RNT, 1) void rec_kernel(float* __restrict__ out)
{
    extern __shared__ float sm[];
    float4* wsa  = (float4*)sm;                  // plane 0: [RSK/4][RNT]
    float4* wsb  = wsa + PLANE;                  // plane 1: [RSK/4][RNT]
    float*  h_sm = sm + 2 * PLANE * 4;           // [2][HH] double-buffered

    const int t_ = threadIdx.x;
    const int u  = t_ >> 1;
    const int r  = t_ & 1;
    const int b  = blockIdx.x >> 1;
    const int g  = blockIdx.x & 1;

    // coalesced load of both smem weight planes
    const float4* wsrc = g_wsm + (size_t)g * 2 * PLANE;
#pragma unroll 4
    for (int i = t_; i < 2 * PLANE; i += RNT) ((float4*)sm)[i] = wsrc[i];

    // coalesced load of reg-part weights
    float w0[RRK], w1[RRK];
    const float2* wrsrc = (const float2*)g_wrg + (size_t)g * RRK * RNT + t_;
#pragma unroll
    for (int j = 0; j < RRK; j++) {
        float2 v = wrsrc[(size_t)j * RNT];
        w0[j] = v.x; w1[j] = v.y;
    }

    h_sm[t_] = 0.f;   // RNT == 2*HH: zeros both h buffers
    float c = 0.f;
    __syncthreads();

    const int c0 = (2 * r) * HH + u;
    const int c1 = (2 * r + 1) * HH + u;
    const float* grow = g_gates + ((size_t)b * TSTEPS) * NG * NGATE + (size_t)g * NGATE;
    float gx0 = grow[c0], gx1 = grow[c1];
    int p = 0;

    for (int t = 0; t < TSTEPS; t++) {
        float nx0 = 0.f, nx1 = 0.f;
        if (t + 1 < TSTEPS) {
            const float* gn = grow + (size_t)(t + 1) * NG * NGATE;
            nx0 = __ldg(gn + c0);
            nx1 = __ldg(gn + c1);
        }

        const float4* h4 = (const float4*)(h_sm + p * HH);
        float a0 = gx0, e0 = 0.f, a1 = gx1, e1 = 0.f;
#pragma unroll
        for (int kk = 0; kk < RSK / 4; kk++) {
            float4 hv = h4[kk];
            float4 wa = wsa[kk * RNT + t_];
            float4 wb = wsb[kk * RNT + t_];
            a0 = fmaf(wa.x, hv.x, a0); e0 = fmaf(wa.y, hv.y, e0);
            a0 = fmaf(wa.z, hv.z, a0); e0 = fmaf(wa.w, hv.w, e0);
            a1 = fmaf(wb.x, hv.x, a1); e1 = fmaf(wb.y, hv.y, e1);
            a1 = fmaf(wb.z, hv.z, a1); e1 = fmaf(wb.w, hv.w, e1);
        }
#pragma unroll
        for (int jj = 0; jj < RRK / 4; jj++) {
            float4 hv = h4[RSK / 4 + jj];
            a0 = fmaf(w0[4*jj+0], hv.x, a0); e0 = fmaf(w0[4*jj+1], hv.y, e0);
            a0 = fmaf(w0[4*jj+2], hv.z, a0); e0 = fmaf(w0[4*jj+3], hv.w, e0);
            a1 = fmaf(w1[4*jj+0], hv.x, a1); e1 = fmaf(w1[4*jj+1], hv.y, e1);
            a1 = fmaf(w1[4*jj+2], hv.z, a1); e1 = fmaf(w1[4*jj+3], hv.w, e1);
        }
        float acc0 = a0 + e0, acc1 = a1 + e1;

        // r=0: acc0=i (sigmoid), acc1=f (sigmoid)
        // r=1: acc0=g (tanh = 2*sigmoid(2x)-1), acc1=o (sigmoid)
        float z0 = r ? 2.f * acc0 : acc0;
        float s0 = __fdividef(1.f, 1.f + __expf(-z0));
        float A0 = r ? fmaf(2.f, s0, -1.f) : s0;
        float A1 = __fdividef(1.f, 1.f + __expf(-acc1));
        float X0 = __shfl_xor_sync(0xFFFFFFFFu, A0, 1);
        float X1 = __shfl_xor_sync(0xFFFFFFFFu, A1, 1);
        float gi = r ? X0 : A0;
        float gf = r ? X1 : A1;
        float gg = r ? A0 : X0;
        float go = r ? A1 : X1;
        c = fmaf(gf, c, gi * gg);
        float th = __fdividef(2.f, 1.f + __expf(-2.f * c)) - 1.f;
        float hval = go * th;

        if (r == 0) {
            h_sm[(p ^ 1) * HH + u] = hval;
            if (STAGE == 1) {
                int i5 = u / NF, f5 = u - i5 * NF;
                g_x2[((size_t)b * TSTEPS + t) * DD + i5 * 10 + g * NF + f5] = hval;
            } else {
                int d = g * HH + u;
                int cc = d / NF, f5 = d - cc * NF;
                out[(((size_t)b * NCH + cc) * TSTEPS + t) * NF + f5] = hval;
            }
        }
        __syncthreads();
        gx0 = nx0; gx1 = nx1;
        p ^= 1;
    }
}

// ---------------- launch ----------------
extern "C" void kernel_launch(void* const* d_in, const int* in_sizes, int n_in,
                              void* d_out, int out_size)
{
    (void)in_sizes; (void)n_in; (void)out_size;
    const float* input = (const float*)d_in[0];
    const float* Wih1  = (const float*)d_in[1];
    const float* Whh1  = (const float*)d_in[2];
    const float* b1    = (const float*)d_in[3];
    const float* Wih2  = (const float*)d_in[4];
    const float* Whh2  = (const float*)d_in[5];
    const float* b2    = (const float*)d_in[6];
    float* out = (float*)d_out;

    cudaFuncSetAttribute(rec_kernel<1>, cudaFuncAttributeMaxDynamicSharedMemorySize, REC_SMEM);
    cudaFuncSetAttribute(rec_kernel<2>, cudaFuncAttributeMaxDynamicSharedMemorySize, REC_SMEM);

    const int n_in_elems = BATCH * NCH * TSTEPS * NF;
    const int n_w = NG * HH * NGATE;
    dim3 gg(BATCH * TSTEPS / 128, NGATE / 64, NG);

    transpose_kernel<<<(n_in_elems + 255) / 256, 256>>>(input);

    prep_kernel<<<(n_w + 255) / 256, 256>>>(Whh1);
    pregemm_kernel<1><<<gg, 256>>>(Wih1, b1);
    rec_kernel<1><<<BATCH * NG, RNT, REC_SMEM>>>(nullptr);

    prep_kernel<<<(n_w + 255) / 256, 256>>>(Whh2);
    pregemm_kernel<2><<<gg, 256>>>(Wih2, b2);
    rec_kernel<2><<<BATCH * NG, RNT, REC_SMEM>>>(out);
}